// round 1
// baseline (speedup 1.0000x reference)
#include <cuda_runtime.h>

#define NB 32
#define NC 64
#define NPIX 16384   // 128*128
#define GRAM_SPLITS 32

__device__ float g_scale;              // gamma / sigma
__device__ float g_G[NB*NC*NC];        // per-batch Gram, accumulated with atomics
__device__ float g_A[NB*NC*NC];        // g_A[b][e][c] = A_b[c][e]  (transposed for float4 reads)

// ---------------------------------------------------------------------------
// Zero the Gram scratch (runs every replay).
__global__ void k_zero() {
    int i = blockIdx.x * blockDim.x + threadIdx.x;   // 128*256 = 32768 float4s
    ((float4*)g_G)[i] = make_float4(0.f, 0.f, 0.f, 0.f);
}

// ---------------------------------------------------------------------------
// sigma = || W * l2norm(W^T u) ||,  g_scale = gamma / sigma
__global__ void k_sigma(const float* __restrict__ W,
                        const float* __restrict__ gamma,
                        const float* __restrict__ u) {
    __shared__ float v[NC];
    __shared__ float red[NC];
    int t = threadIdx.x;

    float s = 0.f;
    for (int c = 0; c < NC; c++) s = fmaf(W[c*NC + t], u[c], s);   // (W^T u)[t]
    v[t] = s;
    red[t] = s * s;
    __syncthreads();
    for (int off = 32; off > 0; off >>= 1) {
        if (t < off) red[t] += red[t + off];
        __syncthreads();
    }
    float nv = fmaxf(sqrtf(red[0]), 1e-12f);
    __syncthreads();                       // all threads read red[0] before reuse

    float w = 0.f;
    for (int c = 0; c < NC; c++) w = fmaf(W[t*NC + c], v[c], w);   // (W v_un)[t]
    w /= nv;
    red[t] = w * w;
    __syncthreads();
    for (int off = 32; off > 0; off >>= 1) {
        if (t < off) red[t] += red[t + off];
        __syncthreads();
    }
    if (t == 0) {
        float sigma = fmaxf(sqrtf(red[0]), 1e-12f);
        g_scale = gamma[0] / sigma;
    }
}

// ---------------------------------------------------------------------------
// Per-batch Gram: G[b][c][d] = sum_n x[b][c][n] * x[b][d][n]
// grid = (GRAM_SPLITS, NB); each CTA handles a 512-pixel chunk via 8 tiles of 64.
// Shared tile xs is [64 rows(c)][16 float4 cols(n)] with XOR swizzle
// col' = col ^ ((row>>2)&7)  -> conflict-free STS.128 writes and LDS.128 reads.
__global__ void __launch_bounds__(256) k_gram(const float* __restrict__ x) {
    __shared__ float4 xs[NC * 16];
    int b = blockIdx.y;
    const float* xb = x + (size_t)b * NC * NPIX;
    int tid = threadIdx.x;
    int tx = tid & 15, ty = tid >> 4;
    int n0 = blockIdx.x * (NPIX / GRAM_SPLITS);      // 512-wide chunk

    float acc[4][4] = {};

    for (int t = 0; t < NPIX / GRAM_SPLITS; t += 64) {
        // cooperative load: 64 c-rows x 64 pixels, coalesced float4 along n
        #pragma unroll
        for (int p = 0; p < 4; p++) {
            int cc = (tid >> 4) + p * 16;
            float4 v = *(const float4*)(xb + (size_t)cc * NPIX + n0 + t + 4 * (tid & 15));
            xs[cc * 16 + ((tid & 15) ^ ((cc >> 2) & 7))] = v;
        }
        __syncthreads();

        int fa = ty & 7;
        int fb = tx & 7;
        #pragma unroll 4
        for (int n4 = 0; n4 < 16; n4++) {
            float4 av[4], bv[4];
            #pragma unroll
            for (int i = 0; i < 4; i++) av[i] = xs[(4*ty + i) * 16 + (n4 ^ fa)];
            #pragma unroll
            for (int j = 0; j < 4; j++) bv[j] = xs[(4*tx + j) * 16 + (n4 ^ fb)];
            #pragma unroll
            for (int i = 0; i < 4; i++) {
                #pragma unroll
                for (int j = 0; j < 4; j++) {
                    acc[i][j] = fmaf(av[i].x, bv[j].x, acc[i][j]);
                    acc[i][j] = fmaf(av[i].y, bv[j].y, acc[i][j]);
                    acc[i][j] = fmaf(av[i].z, bv[j].z, acc[i][j]);
                    acc[i][j] = fmaf(av[i].w, bv[j].w, acc[i][j]);
                }
            }
        }
        __syncthreads();
    }

    float* G = g_G + b * NC * NC;
    #pragma unroll
    for (int i = 0; i < 4; i++)
        #pragma unroll
        for (int j = 0; j < 4; j++)
            atomicAdd(&G[(4*ty + i) * NC + 4*tx + j], acc[i][j]);
}

// ---------------------------------------------------------------------------
// A_b = (gamma/sigma) * (G_b @ W) + I, stored transposed: g_A[b][e][c] = A[c][e]
__global__ void __launch_bounds__(256) k_matA(const float* __restrict__ W) {
    __shared__ float Gs[NC][NC + 1];
    __shared__ float Ws[NC][NC];
    int b = blockIdx.x;
    int tid = threadIdx.x;
    const float* Gg = g_G + b * NC * NC;
    for (int i = tid; i < NC * NC; i += 256) {
        Gs[i >> 6][i & 63] = Gg[i];
        Ws[i >> 6][i & 63] = W[i];
    }
    __syncthreads();
    float s = g_scale;
    int tx = tid & 15, ty = tid >> 4;
    int c0 = 4 * ty, e0 = 4 * tx;
    float acc[4][4] = {};
    for (int d = 0; d < NC; d++) {
        float a0 = Gs[c0 + 0][d], a1 = Gs[c0 + 1][d];
        float a2 = Gs[c0 + 2][d], a3 = Gs[c0 + 3][d];
        float4 w4 = *(const float4*)&Ws[d][e0];
        acc[0][0] = fmaf(a0, w4.x, acc[0][0]); acc[0][1] = fmaf(a0, w4.y, acc[0][1]);
        acc[0][2] = fmaf(a0, w4.z, acc[0][2]); acc[0][3] = fmaf(a0, w4.w, acc[0][3]);
        acc[1][0] = fmaf(a1, w4.x, acc[1][0]); acc[1][1] = fmaf(a1, w4.y, acc[1][1]);
        acc[1][2] = fmaf(a1, w4.z, acc[1][2]); acc[1][3] = fmaf(a1, w4.w, acc[1][3]);
        acc[2][0] = fmaf(a2, w4.x, acc[2][0]); acc[2][1] = fmaf(a2, w4.y, acc[2][1]);
        acc[2][2] = fmaf(a2, w4.z, acc[2][2]); acc[2][3] = fmaf(a2, w4.w, acc[2][3]);
        acc[3][0] = fmaf(a3, w4.x, acc[3][0]); acc[3][1] = fmaf(a3, w4.y, acc[3][1]);
        acc[3][2] = fmaf(a3, w4.z, acc[3][2]); acc[3][3] = fmaf(a3, w4.w, acc[3][3]);
    }
    float* A = g_A + b * NC * NC;
    #pragma unroll
    for (int i = 0; i < 4; i++)
        #pragma unroll
        for (int j = 0; j < 4; j++) {
            int c = c0 + i, e = e0 + j;
            A[e * NC + c] = fmaf(s, acc[i][j], (c == e) ? 1.f : 0.f);
        }
}

// ---------------------------------------------------------------------------
// out[b][c][n] = sum_e A_b[c][e] * x[b][e][n]
// grid = (NPIX/64, NB); each CTA: 64 n-pixels, full 64x64 A in smem.
__global__ void __launch_bounds__(256) k_out(const float* __restrict__ x,
                                             float* __restrict__ out) {
    __shared__ float4 xs[NC * 16];   // x tile, swizzled as in k_gram
    __shared__ float4 As[NC * 16];   // As[e*16 + c4] = g_A[b][e][4*c4 .. +3]
    int b = blockIdx.y;
    int n0 = blockIdx.x * 64;
    const float* xb = x + (size_t)b * NC * NPIX;
    const float4* Ab = (const float4*)(g_A + b * NC * NC);
    int tid = threadIdx.x;
    int tx = tid & 15, ty = tid >> 4;

    for (int i = tid; i < NC * 16; i += 256) As[i] = Ab[i];
    #pragma unroll
    for (int p = 0; p < 4; p++) {
        int cc = (tid >> 4) + p * 16;
        float4 v = *(const float4*)(xb + (size_t)cc * NPIX + n0 + 4 * (tid & 15));
        xs[cc * 16 + ((tid & 15) ^ ((cc >> 2) & 7))] = v;
    }
    __syncthreads();

    float4 acc[4];
    acc[0] = acc[1] = acc[2] = acc[3] = make_float4(0.f, 0.f, 0.f, 0.f);

    #pragma unroll 8
    for (int e = 0; e < NC; e++) {
        float4 a = As[e * 16 + ty];                      // A[4ty..4ty+3][e]
        float4 xv = xs[e * 16 + (tx ^ ((e >> 2) & 7))];  // x[e][n0+4tx..+3]
        acc[0].x = fmaf(a.x, xv.x, acc[0].x); acc[0].y = fmaf(a.x, xv.y, acc[0].y);
        acc[0].z = fmaf(a.x, xv.z, acc[0].z); acc[0].w = fmaf(a.x, xv.w, acc[0].w);
        acc[1].x = fmaf(a.y, xv.x, acc[1].x); acc[1].y = fmaf(a.y, xv.y, acc[1].y);
        acc[1].z = fmaf(a.y, xv.z, acc[1].z); acc[1].w = fmaf(a.y, xv.w, acc[1].w);
        acc[2].x = fmaf(a.z, xv.x, acc[2].x); acc[2].y = fmaf(a.z, xv.y, acc[2].y);
        acc[2].z = fmaf(a.z, xv.z, acc[2].z); acc[2].w = fmaf(a.z, xv.w, acc[2].w);
        acc[3].x = fmaf(a.w, xv.x, acc[3].x); acc[3].y = fmaf(a.w, xv.y, acc[3].y);
        acc[3].z = fmaf(a.w, xv.z, acc[3].z); acc[3].w = fmaf(a.w, xv.w, acc[3].w);
    }

    float* ob = out + (size_t)b * NC * NPIX;
    #pragma unroll
    for (int i = 0; i < 4; i++)
        *(float4*)(ob + (size_t)(4*ty + i) * NPIX + n0 + 4 * tx) = acc[i];
}

// ---------------------------------------------------------------------------
extern "C" void kernel_launch(void* const* d_in, const int* in_sizes, int n_in,
                              void* d_out, int out_size) {
    const float* x     = (const float*)d_in[0];
    const float* W     = (const float*)d_in[1];
    const float* gamma = (const float*)d_in[2];
    const float* u     = (const float*)d_in[3];
    float* out = (float*)d_out;

    k_zero<<<128, 256>>>();
    k_sigma<<<1, 64>>>(W, gamma, u);
    k_gram<<<dim3(GRAM_SPLITS, NB), 256>>>(x);
    k_matA<<<NB, 256>>>(W);
    k_out<<<dim3(NPIX / 64, NB), 256>>>(x, out);
}